// round 2
// baseline (speedup 1.0000x reference)
#include <cuda_runtime.h>
#include <math.h>

#define NP 512
#define GD 64
#define K2STRIDE (4224*64)

// ---------------- scratch (device globals; no allocations) ----------------
__device__ float d_h0[NP*66];                 // layer-0 input features [n][66]
__device__ float d_bufA[NP*64];               // ping-pong layer outputs
__device__ float d_bufB[NP*64];
__device__ float d_t[NP*GD*66];               // t[m][g*ci + i]
__device__ int   d_cnt8[NP*8];                // per-(m, 64-n-chunk) active count
__device__ unsigned short      d_pn[NP*NP];   // neighbor index per slot
__device__ unsigned long long  d_pg[NP*NP];   // 8 packed tap cells (8 bits each; 64 = pad)
__device__ float d_pw[NP*NP*8];               // 8 tap weights (att folded in)
__device__ float d_K2[5*K2STRIDE];            // K rearranged: [(g*ci+i)][o] per layer

// ---------------- prep: feats0 + rearranged kernels ----------------
__global__ void prep_kernel(const float* __restrict__ v, const float* __restrict__ other,
                            const float* __restrict__ k0, const float* __restrict__ k1,
                            const float* __restrict__ k2, const float* __restrict__ k3,
                            const float* __restrict__ k4)
{
    int task = blockIdx.y;
    int stride = gridDim.x * blockDim.x;
    int start = blockIdx.x * blockDim.x + threadIdx.x;
    if (task == 0) {
        for (int e = start; e < NP*66; e += stride) {
            int n = e / 66, i = e - n*66;
            float val;
            if (i == 0)      val = 1.0f;
            else if (i < 4)  val = v[n*3 + (i-1)];
            else             val = other[n*62 + (i-4)];
            d_h0[e] = val;
        }
    } else {
        int l = task - 1;
        const float* src = (l==0)?k0 : (l==1)?k1 : (l==2)?k2 : (l==3)?k3 : k4;
        int ci = (l==0) ? 66 : 64;
        int co = (l==0) ? 32 : ((l==4) ? 6 : 64);
        int tot = GD*ci*co;
        float* dst = d_K2 + l*K2STRIDE;
        for (int e = start; e < tot; e += stride) {
            int o  = e % co;
            int t2 = e / co;
            int i  = t2 % ci;
            int g  = t2 / ci;
            dst[e] = src[(o*ci + i)*GD + g];
        }
    }
}

// ---------------- geometry: compacted pair lists ----------------
__global__ void __launch_bounds__(256) geom_kernel(const float* __restrict__ p,
                                                   const float* __restrict__ mask)
{
    int m = blockIdx.x;
    int tid = threadIdx.x;
    int lane = tid & 31, warp = tid >> 5;   // warp w owns n in [w*64, w*64+64)
    float pmx = p[m*3+0], pmy = p[m*3+1], pmz = p[m*3+2];
    const float INV_R = 1.0f/40.0f;
    const float C4PI  = 1.2732395447351628f;   // 4/pi
    int cnt = 0;
    int cbase = warp*64;
    #pragma unroll
    for (int round = 0; round < 2; round++) {
        int n = cbase + round*32 + lane;
        float rx = (p[n*3+0]-pmx)*INV_R;
        float ry = (p[n*3+1]-pmy)*INV_R;
        float rz = (p[n*3+2]-pmz)*INV_R;
        float r2 = rx*rx + ry*ry + rz*rz;
        float mk = mask[n];
        float t1 = 1.0f - r2;
        bool active = (t1 > 0.0f) && (mk != 0.0f);
        float w8[8];
        unsigned long long gp = 0ull;
        if (active) {
            float att = t1*t1*t1*mk;
            float r = sqrtf(rx*rx + ry*ry + 1e-9f);
            float xs, ys;
            if (rx == 0.0f && ry == 0.0f) { xs = 0.0f; ys = 0.0f; }
            else if (fabsf(ry) <= fabsf(rx)) {
                float s = copysignf(r, rx);
                xs = s;
                ys = C4PI * s * atanf(ry / rx);
            } else {
                float s = copysignf(r, ry);
                ys = s;
                xs = C4PI * s * atanf(rx / ry);
            }
            float zs = rz;
            // grid_sample pixel coords, size 4, align_corners=False: c = 2*g + 1.5
            float cz = 2.0f*zs + 1.5f, cy = 2.0f*ys + 1.5f, cx = 2.0f*xs + 1.5f;
            float fz0 = floorf(cz), fy0 = floorf(cy), fx0 = floorf(cx);
            int iz = (int)fz0, iy = (int)fy0, ix = (int)fx0;
            float fz = cz - fz0, fy = cy - fy0, fx = cx - fx0;
            float wz[2] = {1.0f-fz, fz};
            float wy[2] = {1.0f-fy, fy};
            float wx[2] = {1.0f-fx, fx};
            #pragma unroll
            for (int dz = 0; dz < 2; dz++)
            #pragma unroll
            for (int dy = 0; dy < 2; dy++)
            #pragma unroll
            for (int dx = 0; dx < 2; dx++) {
                int k = dz*4 + dy*2 + dx;
                int z = iz+dz, y = iy+dy, x = ix+dx;
                bool valid = ((unsigned)z < 4u) && ((unsigned)y < 4u) && ((unsigned)x < 4u);
                float w = valid ? (wz[dz]*wy[dy]*wx[dx]*att) : 0.0f;
                int g = valid ? (z*16 + y*4 + x) : 64;   // 64 = dummy pad row
                w8[k] = w;
                gp |= ((unsigned long long)(unsigned)g) << (8*k);
            }
        }
        unsigned bal = __ballot_sync(0xffffffffu, active);
        int pos = cnt + __popc(bal & ((1u << lane) - 1u));
        if (active) {
            int slot = m*NP + cbase + pos;
            d_pn[slot] = (unsigned short)n;
            d_pg[slot] = gp;
            #pragma unroll
            for (int k = 0; k < 8; k++) d_pw[slot*8 + k] = w8[k];
        }
        cnt += __popc(bal);
    }
    if (lane == 0) d_cnt8[m*8 + warp] = cnt;
}

// ---------------- kernel A: scatter-accumulate t + dense tail ----------------
// 128 threads = 64 i-lanes x 2 n-slices; 2 private shared copies of t (rows 0..64, row 64 = pad).
__global__ void __launch_bounds__(128) convA_kernel(
    int finsel, int dorelu, int ci,
    const float* __restrict__ W, const float* __restrict__ bias,
    int outsel, float* __restrict__ dout, int mode)
{
    __shared__ float t4[2*65*66];
    __shared__ float sw[64*8];
    __shared__ unsigned long long sg8[64];
    __shared__ unsigned short snn[64];

    const float* fin = (finsel==0) ? d_h0 : (finsel==1) ? d_bufA : d_bufB;
    float* outbuf = (outsel==0) ? d_bufA : (outsel==1) ? d_bufB : dout;

    int m = blockIdx.x;
    int tid = threadIdx.x;
    int il = tid & 63, sl = tid >> 6;
    int rows = 65*ci;
    for (int idx = tid; idx < 2*rows; idx += 128) t4[idx] = 0.0f;
    float* tsl = t4 + sl*rows;

    for (int c = 0; c < 8; c++) {
        __syncthreads();
        int base = m*NP + c*64;
        if (tid < 64) { snn[tid] = d_pn[base + tid]; sg8[tid] = d_pg[base + tid]; }
        #pragma unroll
        for (int q = 0; q < 4; q++) sw[tid + q*128] = d_pw[base*8 + q*128 + tid];
        __syncthreads();
        int cnt = d_cnt8[m*8 + c];
        for (int s = sl; s < cnt; s += 2) {
            int n = snn[s];
            unsigned long long gp = sg8[s];
            const float* fr = fin + n*ci;
            const float* swp = sw + s*8;
            float w0 = swp[0], w1 = swp[1], w2 = swp[2], w3 = swp[3];
            float w4 = swp[4], w5 = swp[5], w6 = swp[6], w7 = swp[7];
            int o0 = ((int)( gp        & 255ull))*ci;
            int o1 = ((int)((gp >>  8) & 255ull))*ci;
            int o2 = ((int)((gp >> 16) & 255ull))*ci;
            int o3 = ((int)((gp >> 24) & 255ull))*ci;
            int o4 = ((int)((gp >> 32) & 255ull))*ci;
            int o5 = ((int)((gp >> 40) & 255ull))*ci;
            int o6 = ((int)((gp >> 48) & 255ull))*ci;
            int o7 = ((int)((gp >> 56) & 255ull))*ci;
            for (int i = il; i < ci; i += 64) {
                float f = __ldg(fr + i);
                if (dorelu) f = fmaxf(f, 0.0f);
                float* tp = tsl + i;
                float a0 = tp[o0], a1 = tp[o1], a2 = tp[o2], a3 = tp[o3];
                float a4 = tp[o4], a5 = tp[o5], a6 = tp[o6], a7 = tp[o7];
                a0 = fmaf(w0, f, a0); a1 = fmaf(w1, f, a1);
                a2 = fmaf(w2, f, a2); a3 = fmaf(w3, f, a3);
                a4 = fmaf(w4, f, a4); a5 = fmaf(w5, f, a5);
                a6 = fmaf(w6, f, a6); a7 = fmaf(w7, f, a7);
                tp[o0] = a0; tp[o1] = a1; tp[o2] = a2; tp[o3] = a3;
                tp[o4] = a4; tp[o5] = a5; tp[o6] = a6; tp[o7] = a7;
            }
        }
    }
    __syncthreads();
    int s64 = 64*ci;
    for (int idx = tid; idx < s64; idx += 128)
        d_t[m*s64 + idx] = t4[idx] + t4[idx + rows];

    // dense tail: initialize output buffer; conv part atomic-added by convB.
    if (mode == 0) {
        if (tid < 64) {
            float val = 0.0f;
            if (tid >= 32) {
                int o = tid - 32;
                float acc = bias[o];
                for (int i = 0; i < 66; i++) acc = fmaf(fin[m*66 + i], W[o*66 + i], acc);
                val = acc;
            }
            outbuf[m*64 + tid] = val;
        }
    } else if (mode == 1) {
        if (tid < 64) {
            int o = tid;
            float acc = bias[o] + fin[m*64 + o];   // residual (raw, no relu)
            for (int i = 0; i < 64; i++)
                acc = fmaf(fmaxf(fin[m*64 + i], 0.0f), W[o*64 + i], acc);
            outbuf[m*64 + o] = acc;
        }
    } else {
        if (tid < 6) {
            int o = tid;
            float acc = bias[o];
            for (int i = 0; i < 64; i++)
                acc = fmaf(fmaxf(fin[m*64 + i], 0.0f), W[o*64 + i], acc);
            outbuf[m*6 + o] = acc;
        }
    }
}

// ---------------- kernel B: k-split GEMM  out[m][o] += sum_k t[m][k]*K2[k][o] ----------------
#define CB_MT 64
#define CB_NKS 8
__global__ void __launch_bounds__(256) convB_kernel(
    int layer, int ci, int co, int ow, int outsel, float* __restrict__ dout)
{
    __shared__ float sT[32][68];   // [k][m], padded: row stride 68 (16B-aligned, ok banks)
    const float* K2l = d_K2 + layer*K2STRIDE;
    float* outbuf = (outsel==0) ? d_bufA : (outsel==1) ? d_bufB : dout;

    int Ktot = 64*ci;
    int m0 = blockIdx.x * CB_MT;
    int ks = blockIdx.y;
    int kslice = (Ktot + CB_NKS - 1) / CB_NKS;
    int kbeg = ks * kslice;
    int kend = min(Ktot, kbeg + kslice);
    int tid = threadIdx.x;
    int o  = tid & 63;
    int mq = tid >> 6;           // 0..3 ; owns m = m0 + mq*16 + j
    float acc[16];
    #pragma unroll
    for (int j = 0; j < 16; j++) acc[j] = 0.0f;

    for (int kb = kbeg; kb < kend; kb += 32) {
        __syncthreads();
        #pragma unroll
        for (int e = tid; e < 512; e += 256) {
            int ml = e >> 3;     // 0..63
            int kq = e & 7;      // 0..7
            int kk = kb + kq*4;
            float x0=0.f, x1=0.f, x2=0.f, x3=0.f;
            const float* src = d_t + (size_t)(m0+ml)*Ktot + kk;
            if (kk + 3 < kend) {
                float4 vv = *(const float4*)src;
                x0=vv.x; x1=vv.y; x2=vv.z; x3=vv.w;
            } else {
                if (kk+0 < kend) x0 = src[0];
                if (kk+1 < kend) x1 = src[1];
                if (kk+2 < kend) x2 = src[2];
                if (kk+3 < kend) x3 = src[3];
            }
            sT[kq*4+0][ml] = x0; sT[kq*4+1][ml] = x1;
            sT[kq*4+2][ml] = x2; sT[kq*4+3][ml] = x3;
        }
        __syncthreads();
        int klim = min(32, kend - kb);
        for (int k = 0; k < klim; k++) {
            float bval = (o < co) ? K2l[(size_t)(kb+k)*co + o] : 0.0f;
            const float* tr = &sT[k][mq*16];
            #pragma unroll
            for (int jj = 0; jj < 4; jj++) {
                float4 a = *(const float4*)(tr + 4*jj);
                acc[4*jj+0] = fmaf(a.x, bval, acc[4*jj+0]);
                acc[4*jj+1] = fmaf(a.y, bval, acc[4*jj+1]);
                acc[4*jj+2] = fmaf(a.z, bval, acc[4*jj+2]);
                acc[4*jj+3] = fmaf(a.w, bval, acc[4*jj+3]);
            }
        }
    }
    if (o < co) {
        #pragma unroll
        for (int j = 0; j < 16; j++) {
            int m = m0 + mq*16 + j;
            atomicAdd(outbuf + (size_t)m*ow + o, acc[j]);
        }
    }
}

// ---------------- host ----------------
extern "C" void kernel_launch(void* const* d_in, const int* in_sizes, int n_in,
                              void* d_out, int out_size)
{
    const float* p     = (const float*)d_in[0];
    const float* v     = (const float*)d_in[1];
    const float* other = (const float*)d_in[2];
    const float* mask  = (const float*)d_in[3];
    const float* kf    = (const float*)d_in[4];
    const float* Wf    = (const float*)d_in[5];
    const float* bf    = (const float*)d_in[6];
    const float* k1    = (const float*)d_in[7];
    const float* W1    = (const float*)d_in[8];
    const float* b1    = (const float*)d_in[9];
    const float* k2    = (const float*)d_in[10];
    const float* W2    = (const float*)d_in[11];
    const float* b2    = (const float*)d_in[12];
    const float* k3    = (const float*)d_in[13];
    const float* W3    = (const float*)d_in[14];
    const float* b3    = (const float*)d_in[15];
    const float* k4    = (const float*)d_in[16];
    const float* W4    = (const float*)d_in[17];
    const float* b4    = (const float*)d_in[18];
    float* out = (float*)d_out;

    prep_kernel<<<dim3(64,6), 256>>>(v, other, kf, k1, k2, k3, k4);
    geom_kernel<<<NP, 256>>>(p, mask);

    // layer 0: fin=h0(sel 0), no relu, ci=66, out -> bufA(sel 0), conv co=32 into cols 0..31
    convA_kernel<<<NP, 128>>>(0, 0, 66, Wf, bf, 0, out, 0);
    convB_kernel<<<dim3(NP/CB_MT, CB_NKS), 256>>>(0, 66, 32, 64, 0, out);

    // layer 1: fin=bufA(1), relu, ci=64, out -> bufB(1)
    convA_kernel<<<NP, 128>>>(1, 1, 64, W1, b1, 1, out, 1);
    convB_kernel<<<dim3(NP/CB_MT, CB_NKS), 256>>>(1, 64, 64, 64, 1, out);

    // layer 2: fin=bufB(2) -> bufA(0)
    convA_kernel<<<NP, 128>>>(2, 1, 64, W2, b2, 0, out, 1);
    convB_kernel<<<dim3(NP/CB_MT, CB_NKS), 256>>>(2, 64, 64, 64, 0, out);

    // layer 3: fin=bufA(1) -> bufB(1)
    convA_kernel<<<NP, 128>>>(1, 1, 64, W3, b3, 1, out, 1);
    convB_kernel<<<dim3(NP/CB_MT, CB_NKS), 256>>>(3, 64, 64, 64, 1, out);

    // layer 4: fin=bufB(2) -> d_out (sel 2), co=6, no residual
    convA_kernel<<<NP, 128>>>(2, 1, 64, W4, b4, 2, out, 2);
    convB_kernel<<<dim3(NP/CB_MT, CB_NKS), 256>>>(4, 64, 6, 6, 2, out);
}

// round 4
// speedup vs baseline: 1.7442x; 1.7442x over previous
#include <cuda_runtime.h>
#include <math.h>

#define NP 512
#define GD 64
#define K2STRIDE (4224*64)
#define CB_BK 32
#define CB_NKS 18

// ---------------- scratch (device globals; no allocations) ----------------
__device__ float d_h0[NP*66];                 // layer-0 input features [n][66]
__device__ float d_bufA[NP*64];               // ping-pong layer outputs
__device__ float d_bufB[NP*64];
__device__ float d_t[NP*GD*66];               // t[m][g*ci + i]
__device__ int   d_cnt8[NP*8];                // per-(m, 64-n-chunk) active count
__device__ unsigned short      d_pn[NP*NP];   // neighbor index per slot
__device__ unsigned long long  d_pg[NP*NP];   // 8 packed tap cells (8 bits each; 64 = pad)
__device__ float d_pw[NP*NP*8];               // 8 tap weights (att folded in)
__device__ float d_K2[5*K2STRIDE];            // K rearranged: [(g*ci+i)][o] per layer

// ---------------- prep: feats0 + rearranged kernels ----------------
__global__ void prep_kernel(const float* __restrict__ v, const float* __restrict__ other,
                            const float* __restrict__ k0, const float* __restrict__ k1,
                            const float* __restrict__ k2, const float* __restrict__ k3,
                            const float* __restrict__ k4)
{
    int task = blockIdx.y;
    int stride = gridDim.x * blockDim.x;
    int start = blockIdx.x * blockDim.x + threadIdx.x;
    if (task == 0) {
        for (int e = start; e < NP*66; e += stride) {
            int n = e / 66, i = e - n*66;
            float val;
            if (i == 0)      val = 1.0f;
            else if (i < 4)  val = v[n*3 + (i-1)];
            else             val = other[n*62 + (i-4)];
            d_h0[e] = val;
        }
    } else {
        int l = task - 1;
        const float* src = (l==0)?k0 : (l==1)?k1 : (l==2)?k2 : (l==3)?k3 : k4;
        int ci = (l==0) ? 66 : 64;
        int co = (l==0) ? 32 : ((l==4) ? 6 : 64);
        int tot = GD*ci*co;
        float* dst = d_K2 + l*K2STRIDE;
        for (int e = start; e < tot; e += stride) {
            int o  = e % co;
            int t2 = e / co;
            int i  = t2 % ci;
            int g  = t2 / ci;
            dst[e] = src[(o*ci + i)*GD + g];
        }
    }
}

// ---------------- geometry: compacted pair lists ----------------
__global__ void __launch_bounds__(256) geom_kernel(const float* __restrict__ p,
                                                   const float* __restrict__ mask)
{
    int m = blockIdx.x;
    int tid = threadIdx.x;
    int lane = tid & 31, warp = tid >> 5;   // warp w owns n in [w*64, w*64+64)
    float pmx = p[m*3+0], pmy = p[m*3+1], pmz = p[m*3+2];
    const float INV_R = 1.0f/40.0f;
    const float C4PI  = 1.2732395447351628f;   // 4/pi
    int cnt = 0;
    int cbase = warp*64;
    #pragma unroll
    for (int round = 0; round < 2; round++) {
        int n = cbase + round*32 + lane;
        float rx = (p[n*3+0]-pmx)*INV_R;
        float ry = (p[n*3+1]-pmy)*INV_R;
        float rz = (p[n*3+2]-pmz)*INV_R;
        float r2 = rx*rx + ry*ry + rz*rz;
        float mk = mask[n];
        float t1 = 1.0f - r2;
        bool active = (t1 > 0.0f) && (mk != 0.0f);
        float w8[8];
        unsigned long long gp = 0ull;
        if (active) {
            float att = t1*t1*t1*mk;
            float r = sqrtf(rx*rx + ry*ry + 1e-9f);
            float xs, ys;
            if (rx == 0.0f && ry == 0.0f) { xs = 0.0f; ys = 0.0f; }
            else if (fabsf(ry) <= fabsf(rx)) {
                float s = copysignf(r, rx);
                xs = s;
                ys = C4PI * s * atanf(ry / rx);
            } else {
                float s = copysignf(r, ry);
                ys = s;
                xs = C4PI * s * atanf(rx / ry);
            }
            float zs = rz;
            // grid_sample pixel coords, size 4, align_corners=False: c = 2*g + 1.5
            float cz = 2.0f*zs + 1.5f, cy = 2.0f*ys + 1.5f, cx = 2.0f*xs + 1.5f;
            float fz0 = floorf(cz), fy0 = floorf(cy), fx0 = floorf(cx);
            int iz = (int)fz0, iy = (int)fy0, ix = (int)fx0;
            float fz = cz - fz0, fy = cy - fy0, fx = cx - fx0;
            float wz[2] = {1.0f-fz, fz};
            float wy[2] = {1.0f-fy, fy};
            float wx[2] = {1.0f-fx, fx};
            #pragma unroll
            for (int dz = 0; dz < 2; dz++)
            #pragma unroll
            for (int dy = 0; dy < 2; dy++)
            #pragma unroll
            for (int dx = 0; dx < 2; dx++) {
                int k = dz*4 + dy*2 + dx;
                int z = iz+dz, y = iy+dy, x = ix+dx;
                bool valid = ((unsigned)z < 4u) && ((unsigned)y < 4u) && ((unsigned)x < 4u);
                float w = valid ? (wz[dz]*wy[dy]*wx[dx]*att) : 0.0f;
                int g = valid ? (z*16 + y*4 + x) : 64;   // 64 = dummy pad row
                w8[k] = w;
                gp |= ((unsigned long long)(unsigned)g) << (8*k);
            }
        }
        unsigned bal = __ballot_sync(0xffffffffu, active);
        int pos = cnt + __popc(bal & ((1u << lane) - 1u));
        if (active) {
            int slot = m*NP + cbase + pos;
            d_pn[slot] = (unsigned short)n;
            d_pg[slot] = gp;
            #pragma unroll
            for (int k = 0; k < 8; k++) d_pw[slot*8 + k] = w8[k];
        }
        cnt += __popc(bal);
    }
    if (lane == 0) d_cnt8[m*8 + warp] = cnt;
}

// ---------------- kernel A: scatter-accumulate t + dense tail ----------------
// 128 threads = 64 i-lanes x 2 n-slices; 2 private shared copies of t (rows 0..64, row 64 = pad).
__global__ void __launch_bounds__(128) convA_kernel(
    int finsel, int dorelu, int ci,
    const float* __restrict__ W, const float* __restrict__ bias,
    int outsel, float* __restrict__ dout, int mode)
{
    __shared__ float t4[2*65*66];
    __shared__ float sw[64*8];
    __shared__ unsigned long long sg8[64];
    __shared__ unsigned short snn[64];

    const float* fin = (finsel==0) ? d_h0 : (finsel==1) ? d_bufA : d_bufB;
    float* outbuf = (outsel==0) ? d_bufA : (outsel==1) ? d_bufB : dout;

    int m = blockIdx.x;
    int tid = threadIdx.x;
    int il = tid & 63, sl = tid >> 6;
    int rows = 65*ci;
    for (int idx = tid; idx < 2*rows; idx += 128) t4[idx] = 0.0f;
    float* tsl = t4 + sl*rows;

    for (int c = 0; c < 8; c++) {
        __syncthreads();
        int base = m*NP + c*64;
        if (tid < 64) { snn[tid] = d_pn[base + tid]; sg8[tid] = d_pg[base + tid]; }
        #pragma unroll
        for (int q = 0; q < 4; q++) sw[tid + q*128] = d_pw[base*8 + q*128 + tid];
        __syncthreads();
        int cnt = d_cnt8[m*8 + c];
        for (int s = sl; s < cnt; s += 2) {
            int n = snn[s];
            unsigned long long gp = sg8[s];
            const float* fr = fin + n*ci;
            const float* swp = sw + s*8;
            float w0 = swp[0], w1 = swp[1], w2 = swp[2], w3 = swp[3];
            float w4 = swp[4], w5 = swp[5], w6 = swp[6], w7 = swp[7];
            int o0 = ((int)( gp        & 255ull))*ci;
            int o1 = ((int)((gp >>  8) & 255ull))*ci;
            int o2 = ((int)((gp >> 16) & 255ull))*ci;
            int o3 = ((int)((gp >> 24) & 255ull))*ci;
            int o4 = ((int)((gp >> 32) & 255ull))*ci;
            int o5 = ((int)((gp >> 40) & 255ull))*ci;
            int o6 = ((int)((gp >> 48) & 255ull))*ci;
            int o7 = ((int)((gp >> 56) & 255ull))*ci;
            for (int i = il; i < ci; i += 64) {
                float f = __ldg(fr + i);
                if (dorelu) f = fmaxf(f, 0.0f);
                float* tp = tsl + i;
                float a0 = tp[o0], a1 = tp[o1], a2 = tp[o2], a3 = tp[o3];
                float a4 = tp[o4], a5 = tp[o5], a6 = tp[o6], a7 = tp[o7];
                a0 = fmaf(w0, f, a0); a1 = fmaf(w1, f, a1);
                a2 = fmaf(w2, f, a2); a3 = fmaf(w3, f, a3);
                a4 = fmaf(w4, f, a4); a5 = fmaf(w5, f, a5);
                a6 = fmaf(w6, f, a6); a7 = fmaf(w7, f, a7);
                tp[o0] = a0; tp[o1] = a1; tp[o2] = a2; tp[o3] = a3;
                tp[o4] = a4; tp[o5] = a5; tp[o6] = a6; tp[o7] = a7;
            }
        }
    }
    __syncthreads();
    int s64 = 64*ci;
    for (int idx = tid; idx < s64; idx += 128)
        d_t[m*s64 + idx] = t4[idx] + t4[idx + rows];

    // dense tail: initialize output buffer; conv part atomic-added by convB.
    if (mode == 0) {
        if (tid < 64) {
            float val = 0.0f;
            if (tid >= 32) {
                int o = tid - 32;
                float acc = bias[o];
                for (int i = 0; i < 66; i++) acc = fmaf(fin[m*66 + i], W[o*66 + i], acc);
                val = acc;
            }
            outbuf[m*64 + tid] = val;
        }
    } else if (mode == 1) {
        if (tid < 64) {
            int o = tid;
            float acc = bias[o] + fin[m*64 + o];   // residual (raw, no relu)
            for (int i = 0; i < 64; i++)
                acc = fmaf(fmaxf(fin[m*64 + i], 0.0f), W[o*64 + i], acc);
            outbuf[m*64 + o] = acc;
        }
    } else {
        if (tid < 6) {
            int o = tid;
            float acc = bias[o];
            for (int i = 0; i < 64; i++)
                acc = fmaf(fmaxf(fin[m*64 + i], 0.0f), W[o*64 + i], acc);
            outbuf[m*6 + o] = acc;
        }
    }
}

// ---------------- kernel B: k-split tiled GEMM  out[m][o] += sum_k t[m][k]*K2[k][o] --------
// Block: 64x64 output tile, BK=32 slab, register-prefetch double buffering.
// Grid: (8 m-tiles, CB_NKS k-slices). Strided chunk assignment.
__global__ void __launch_bounds__(256) convB_kernel(
    int layer, int Ktot, int co, int ow, int outsel, float* __restrict__ dout)
{
    __shared__ float sA[CB_BK][68];   // [k][m]
    __shared__ float sB[CB_BK][64];   // [k][o]
    const float* K2l = d_K2 + layer*K2STRIDE;
    float* outbuf = (outsel==0) ? d_bufA : (outsel==1) ? d_bufB : dout;

    int m0 = blockIdx.x * 64;
    int tid = threadIdx.x;
    int nchunks = (Ktot + CB_BK - 1) / CB_BK;

    // A-load mapping: thread loads 8 consecutive k for one m row
    int mA = tid & 63;
    int kA = (tid >> 6) * 8;
    const float* tbase = d_t + (size_t)(m0 + mA) * Ktot;
    // B-load mapping: thread loads 8 consecutive o for one k row
    int kB = tid >> 3;
    int oB = (tid & 7) * 8;

    // compute micro-tile 4x4
    int tx = (tid & 15) * 4;
    int ty = (tid >> 4) * 4;

    float acc[16];
    #pragma unroll
    for (int j = 0; j < 16; j++) acc[j] = 0.0f;

    float ra[8], rb[8];

    int c = blockIdx.y;
    // prefetch first chunk
    {
        int kb = c * CB_BK;
        int ka0 = kb + kA;
        if (ka0 + 7 < Ktot) {
            float4 v0 = *(const float4*)(tbase + ka0);
            float4 v1 = *(const float4*)(tbase + ka0 + 4);
            ra[0]=v0.x; ra[1]=v0.y; ra[2]=v0.z; ra[3]=v0.w;
            ra[4]=v1.x; ra[5]=v1.y; ra[6]=v1.z; ra[7]=v1.w;
        } else {
            #pragma unroll
            for (int j = 0; j < 8; j++) ra[j] = (ka0 + j < Ktot) ? tbase[ka0 + j] : 0.0f;
        }
        int kg = kb + kB;
        if (co == 64 && kg < Ktot) {
            const float* bp = K2l + (size_t)kg*64 + oB;
            float4 v0 = *(const float4*)bp;
            float4 v1 = *(const float4*)(bp + 4);
            rb[0]=v0.x; rb[1]=v0.y; rb[2]=v0.z; rb[3]=v0.w;
            rb[4]=v1.x; rb[5]=v1.y; rb[6]=v1.z; rb[7]=v1.w;
        } else {
            #pragma unroll
            for (int j = 0; j < 8; j++)
                rb[j] = (kg < Ktot && (oB + j) < co) ? K2l[(size_t)kg*co + oB + j] : 0.0f;
        }
    }

    while (c < nchunks) {
        #pragma unroll
        for (int j = 0; j < 8; j++) sA[kA + j][mA] = ra[j];
        #pragma unroll
        for (int j = 0; j < 8; j++) sB[kB][oB + j] = rb[j];
        __syncthreads();

        int cn = c + CB_NKS;
        if (cn < nchunks) {
            int kb = cn * CB_BK;
            int ka0 = kb + kA;
            if (ka0 + 7 < Ktot) {
                float4 v0 = *(const float4*)(tbase + ka0);
                float4 v1 = *(const float4*)(tbase + ka0 + 4);
                ra[0]=v0.x; ra[1]=v0.y; ra[2]=v0.z; ra[3]=v0.w;
                ra[4]=v1.x; ra[5]=v1.y; ra[6]=v1.z; ra[7]=v1.w;
            } else {
                #pragma unroll
                for (int j = 0; j < 8; j++) ra[j] = (ka0 + j < Ktot) ? tbase[ka0 + j] : 0.0f;
            }
            int kg = kb + kB;
            if (co == 64 && kg < Ktot) {
                const float* bp = K2l + (size_t)kg*64 + oB;
                float4 v0 = *(const float4*)bp;
                float4 v1 = *(const float4*)(bp + 4);
                rb[0]=v0.x; rb[1]=v0.y; rb[2]=v0.z; rb[3]=v0.w;
                rb[4]=v1.x; rb[5]=v1.y; rb[6]=v1.z; rb[7]=v1.w;
            } else {
                #pragma unroll
                for (int j = 0; j < 8; j++)
                    rb[j] = (kg < Ktot && (oB + j) < co) ? K2l[(size_t)kg*co + oB + j] : 0.0f;
            }
        }

        #pragma unroll
        for (int k = 0; k < CB_BK; k++) {
            float4 b4 = *(const float4*)&sB[k][tx];
            float4 a4 = *(const float4*)&sA[k][ty];
            acc[ 0] = fmaf(a4.x, b4.x, acc[ 0]);
            acc[ 1] = fmaf(a4.x, b4.y, acc[ 1]);
            acc[ 2] = fmaf(a4.x, b4.z, acc[ 2]);
            acc[ 3] = fmaf(a4.x, b4.w, acc[ 3]);
            acc[ 4] = fmaf(a4.y, b4.x, acc[ 4]);
            acc[ 5] = fmaf(a4.y, b4.y, acc[ 5]);
            acc[ 6] = fmaf(a4.y, b4.z, acc[ 6]);
            acc[ 7] = fmaf(a4.y, b4.w, acc[ 7]);
            acc[ 8] = fmaf(a4.z, b4.x, acc[ 8]);
            acc[ 9] = fmaf(a4.z, b4.y, acc[ 9]);
            acc[10] = fmaf(a4.z, b4.z, acc[10]);
            acc[11] = fmaf(a4.z, b4.w, acc[11]);
            acc[12] = fmaf(a4.w, b4.x, acc[12]);
            acc[13] = fmaf(a4.w, b4.y, acc[13]);
            acc[14] = fmaf(a4.w, b4.z, acc[14]);
            acc[15] = fmaf(a4.w, b4.w, acc[15]);
        }
        __syncthreads();
        c = cn;
    }

    #pragma unroll
    for (int j = 0; j < 4; j++) {
        int m = m0 + ty + j;
        #pragma unroll
        for (int cc = 0; cc < 4; cc++) {
            int o = tx + cc;
            if (o < co) atomicAdd(outbuf + (size_t)m*ow + o, acc[j*4 + cc]);
        }
    }
}

// ---------------- host ----------------
extern "C" void kernel_launch(void* const* d_in, const int* in_sizes, int n_in,
                              void* d_out, int out_size)
{
    const float* p     = (const float*)d_in[0];
    const float* v     = (const float*)d_in[1];
    const float* other = (const float*)d_in[2];
    const float* mask  = (const float*)d_in[3];
    const float* kf    = (const float*)d_in[4];
    const float* Wf    = (const float*)d_in[5];
    const float* bf    = (const float*)d_in[6];
    const float* k1    = (const float*)d_in[7];
    const float* W1    = (const float*)d_in[8];
    const float* b1    = (const float*)d_in[9];
    const float* k2    = (const float*)d_in[10];
    const float* W2    = (const float*)d_in[11];
    const float* b2    = (const float*)d_in[12];
    const float* k3    = (const float*)d_in[13];
    const float* W3    = (const float*)d_in[14];
    const float* b3    = (const float*)d_in[15];
    const float* k4    = (const float*)d_in[16];
    const float* W4    = (const float*)d_in[17];
    const float* b4    = (const float*)d_in[18];
    float* out = (float*)d_out;

    prep_kernel<<<dim3(64,6), 256>>>(v, other, kf, k1, k2, k3, k4);
    geom_kernel<<<NP, 256>>>(p, mask);

    // layer 0: fin=h0(sel 0), no relu, ci=66, out -> bufA(sel 0), conv co=32 into cols 0..31
    convA_kernel<<<NP, 128>>>(0, 0, 66, Wf, bf, 0, out, 0);
    convB_kernel<<<dim3(8, CB_NKS), 256>>>(0, 4224, 32, 64, 0, out);

    // layer 1: fin=bufA(1), relu, ci=64, out -> bufB(1)
    convA_kernel<<<NP, 128>>>(1, 1, 64, W1, b1, 1, out, 1);
    convB_kernel<<<dim3(8, CB_NKS), 256>>>(1, 4096, 64, 64, 1, out);

    // layer 2: fin=bufB(2) -> bufA(0)
    convA_kernel<<<NP, 128>>>(2, 1, 64, W2, b2, 0, out, 1);
    convB_kernel<<<dim3(8, CB_NKS), 256>>>(2, 4096, 64, 64, 0, out);

    // layer 3: fin=bufA(1) -> bufB(1)
    convA_kernel<<<NP, 128>>>(1, 1, 64, W3, b3, 1, out, 1);
    convB_kernel<<<dim3(8, CB_NKS), 256>>>(3, 4096, 64, 64, 1, out);

    // layer 4: fin=bufB(2) -> d_out (sel 2), co=6, no residual
    convA_kernel<<<NP, 128>>>(2, 1, 64, W4, b4, 2, out, 2);
    convB_kernel<<<dim3(8, CB_NKS), 256>>>(4, 4096, 6, 6, 2, out);
}